// round 4
// baseline (speedup 1.0000x reference)
#include <cuda_runtime.h>
#include <math.h>

#define TT 2048
#define BB 16
#define NN 2048
#define HH 1024
#define SPL 8
#define CHUNK 256   // 2048/8, = 32 macro-iters of 8 timesteps exactly
#define THR 512     // k_main threads (16 warps)

// scratch (device globals: no allocation allowed in kernel_launch)
__device__ float g_decfea[BB*NN];
__device__ float g_scores[TT*BB];
__device__ float g_m[BB*SPL];
__device__ float g_z[BB*SPL];
__device__ float g_acc[BB*SPL*NN];
__device__ unsigned char g_mask8[TT*BB];

// single-MUFU tanh (sm_75+), abs err ~2e-4 — fine vs 1e-3 threshold
__device__ __forceinline__ float tanhfast(float x){
    float y;
    asm("tanh.approx.f32 %0, %1;" : "=f"(y) : "f"(x));
    return y;
}

// ---------------------------------------------------------------------------
// Kernel 1: dec_fea[b,n] = dot(dec[b,:], Wd[n,:]) + bd[n].
// Also converts the padding mask to uint8 (dtype auto-detected): 128 blocks
// x 256 threads = exactly TT*BB lanes, one element each.
// ---------------------------------------------------------------------------
__global__ void k_decfea(const float* __restrict__ dec,
                         const float* __restrict__ Wd,
                         const float* __restrict__ bd,
                         const unsigned char* __restrict__ mraw){
    // ---- mask conversion (independent of the GEMM below) ----
    {
        const unsigned int* w = (const unsigned int*)mraw;
        int is_word = 1;   // int32 (0/1) or float32 (0.0/1.0) storage
        #pragma unroll
        for (int i = 0; i < 32; ++i){
            unsigned int x = w[i];
            if (x != 0u && x != 1u && x != 0x3F800000u) is_word = 0;
        }
        int idx = blockIdx.x*256 + threadIdx.x;
        unsigned char mv = is_word ? (unsigned char)(w[idx] != 0u)
                                   : (unsigned char)(mraw[idx] != 0);
        g_mask8[idx] = mv;
    }

    __shared__ float sdec[8*HH];       // 32 KB
    __shared__ float sred[8][256];     // 8 KB
    int tid  = threadIdx.x;
    int wid  = tid >> 5, lane = tid & 31;
    int nbase = blockIdx.x * 16;
    for (int half = 0; half < 2; ++half){
        const float4* dg = (const float4*)(dec + half*8*HH);
        float4* sg = (float4*)sdec;
        #pragma unroll
        for (int i = 0; i < 8; ++i) sg[tid + i*256] = dg[tid + i*256];
        __syncthreads();
        for (int r = 0; r < 16; ++r){
            int n = nbase + r;
            float4 w = ((const float4*)(Wd + (size_t)n*HH))[tid];
            float a[8];
            #pragma unroll
            for (int b = 0; b < 8; ++b){
                float4 d = ((const float4*)(sdec + b*HH))[tid];
                a[b] = w.x*d.x + w.y*d.y + w.z*d.z + w.w*d.w;
            }
            #pragma unroll
            for (int b = 0; b < 8; ++b) sred[b][tid] = a[b];
            __syncthreads();
            float vsum = 0.f;
            #pragma unroll
            for (int k = 0; k < 8; ++k) vsum += sred[wid][lane + 32*k];
            #pragma unroll
            for (int off = 16; off; off >>= 1)
                vsum += __shfl_xor_sync(0xffffffffu, vsum, off);
            if (lane == 0) g_decfea[(half*8 + wid)*NN + n] = vsum + bd[n];
            __syncthreads();
        }
    }
}

// ---------------------------------------------------------------------------
// Kernel 2: fused scores + online softmax + context partial (flash-style).
// grid (SPL, BB); 512 threads; each thread owns 4 contiguous n.
// 8 timesteps per macro-iter (2 barriers / 8 t); 1-iter register prefetch.
// ---------------------------------------------------------------------------
__global__ __launch_bounds__(THR, 1) void k_main(
    const float* __restrict__ enc,
    const float* __restrict__ cov,
    const float* __restrict__ wc,
    const float* __restrict__ v)
{
    __shared__ float scov[CHUNK];
    __shared__ unsigned char smask[CHUNK];
    __shared__ float sred[16][9];     // [warp][score], padded: conflict-free
    __shared__ float sbc[8];
    int tid  = threadIdx.x;
    int wid  = tid >> 5, lane = tid & 31;
    int sp = blockIdx.x, b = blockIdx.y;
    int t0 = sp * CHUNK;

    for (int i = tid; i < CHUNK; i += THR){
        scov[i]  = cov[(t0 + i)*BB + b];
        smask[i] = g_mask8[(t0 + i)*BB + b];
    }
    int n0 = tid * 4;
    float4 df = *(const float4*)(g_decfea + b*NN + n0);
    float4 w  = *(const float4*)(wc + n0);
    float4 vv = *(const float4*)(v + n0);

    float m = -INFINITY, Z = 0.f;
    float4 A = make_float4(0.f,0.f,0.f,0.f);
    __syncthreads();

    // prefetch batch 0 (8 rows)
    float4 c[8];
    #pragma unroll
    for (int i = 0; i < 8; ++i)
        c[i] = *(const float4*)(enc + ((size_t)(t0+i)*BB + b)*NN + n0);

    const int NB = CHUNK/8;   // 32
    for (int it = 0; it < NB; ++it){
        int tb = t0 + it*8;
        bool havenext = (it + 1 < NB);
        float4 x[8];
        if (havenext){
            #pragma unroll
            for (int i = 0; i < 8; ++i)
                x[i] = *(const float4*)(enc + ((size_t)(tb+8+i)*BB + b)*NN + n0);
        }
        // per-thread partial dot for each of 8 timesteps
        float part[8];
        #pragma unroll
        for (int i = 0; i < 8; ++i){
            float cv = scov[it*8 + i];
            float p;
            p  = tanhfast(fmaf(cv, w.x, c[i].x + df.x)) * vv.x;
            p += tanhfast(fmaf(cv, w.y, c[i].y + df.y)) * vv.y;
            p += tanhfast(fmaf(cv, w.z, c[i].z + df.z)) * vv.z;
            p += tanhfast(fmaf(cv, w.w, c[i].w + df.w)) * vv.w;
            part[i] = p;
        }
        // stage 1: warp reduce 8 partials
        #pragma unroll
        for (int i = 0; i < 8; ++i)
            #pragma unroll
            for (int off = 16; off; off >>= 1)
                part[i] += __shfl_xor_sync(0xffffffffu, part[i], off);
        if (lane == 0){
            #pragma unroll
            for (int i = 0; i < 8; ++i) sred[wid][i] = part[i];
        }
        __syncthreads();
        // stage 2: 128 threads, 16-lane groups, one score each
        if (tid < 128){
            int s  = tid >> 4;             // score 0..7
            int ww = tid & 15;             // warp 0..15
            float val = sred[ww][s];
            val += __shfl_xor_sync(0xffffffffu, val, 1);
            val += __shfl_xor_sync(0xffffffffu, val, 2);
            val += __shfl_xor_sync(0xffffffffu, val, 4);
            val += __shfl_xor_sync(0xffffffffu, val, 8);
            if (ww == 0) sbc[s] = val;
        }
        __syncthreads();
        float s[8];
        #pragma unroll
        for (int i = 0; i < 8; ++i)
            s[i] = smask[it*8 + i] ? -INFINITY : sbc[i];
        if (tid < 8) g_scores[(tb + tid)*BB + b] = s[tid];

        // online softmax update (uniform branch across the block)
        float m2 = m;
        #pragma unroll
        for (int i = 0; i < 8; ++i) m2 = fmaxf(m2, s[i]);
        if (m2 != -INFINITY){
            float sc = __expf(m - m2);             // m==-inf -> 0 (A still 0)
            float p[8];
            #pragma unroll
            for (int i = 0; i < 8; ++i) p[i] = __expf(s[i] - m2);
            float zs = 0.f;
            #pragma unroll
            for (int i = 0; i < 8; ++i) zs += p[i];
            Z = Z*sc + zs;
            float ax = A.x*sc, ay = A.y*sc, az = A.z*sc, aw = A.w*sc;
            #pragma unroll
            for (int i = 0; i < 8; ++i){
                ax = fmaf(p[i], c[i].x, ax);
                ay = fmaf(p[i], c[i].y, ay);
                az = fmaf(p[i], c[i].z, az);
                aw = fmaf(p[i], c[i].w, aw);
            }
            A.x = ax; A.y = ay; A.z = az; A.w = aw;
            m = m2;
        }
        if (havenext){
            #pragma unroll
            for (int i = 0; i < 8; ++i) c[i] = x[i];
        }
    }
    if (tid == 0){
        g_m[b*SPL + sp] = m;
        g_z[b*SPL + sp] = Z;
    }
    *(float4*)(g_acc + (size_t)(b*SPL + sp)*NN + n0) = A;
}

// ---------------------------------------------------------------------------
// Kernel 3: combine. blocks 0..15: context c[b,:]. blocks 16..47: attn +
// coverage over the flat (t*16+b) index — fully coalesced.
// ---------------------------------------------------------------------------
__global__ void k_combine(const float* __restrict__ cov,
                          float* __restrict__ out){
    int tid = threadIdx.x;
    if (blockIdx.x < BB){
        // ---- context for batch b ----
        int b = blockIdx.x;
        __shared__ float sw[SPL];
        if (tid < 32){
            float mv = (tid < SPL) ? g_m[b*SPL + tid] : -INFINITY;
            float zv = (tid < SPL) ? g_z[b*SPL + tid] : 0.f;
            float M = mv;
            #pragma unroll
            for (int off = 16; off; off >>= 1)
                M = fmaxf(M, __shfl_xor_sync(0xffffffffu, M, off));
            float zz = zv * __expf(mv - M);
            float Zs = zz;
            #pragma unroll
            for (int off = 16; off; off >>= 1)
                Zs += __shfl_xor_sync(0xffffffffu, Zs, off);
            float inv = 1.0f / Zs;
            if (tid < SPL) sw[tid] = __expf(mv - M) * inv;
        }
        __syncthreads();
        int n0 = tid * 8;
        float4 r0 = make_float4(0.f,0.f,0.f,0.f);
        float4 r1 = make_float4(0.f,0.f,0.f,0.f);
        #pragma unroll
        for (int s = 0; s < SPL; ++s){
            const float4* p = (const float4*)(g_acc + (size_t)(b*SPL + s)*NN + n0);
            float wgt = sw[s];
            float4 x = p[0], y = p[1];
            r0.x = fmaf(wgt, x.x, r0.x); r0.y = fmaf(wgt, x.y, r0.y);
            r0.z = fmaf(wgt, x.z, r0.z); r0.w = fmaf(wgt, x.w, r0.w);
            r1.x = fmaf(wgt, y.x, r1.x); r1.y = fmaf(wgt, y.y, r1.y);
            r1.z = fmaf(wgt, y.z, r1.z); r1.w = fmaf(wgt, y.w, r1.w);
        }
        float4* co = (float4*)(out + b*NN + n0);
        co[0] = r0; co[1] = r1;
    } else {
        // ---- attn_dist + coverage_out, flat-indexed (coalesced) ----
        __shared__ float sM[BB], sInv[BB];
        if (tid < BB){
            int b = tid;
            float M = -INFINITY;
            #pragma unroll
            for (int s = 0; s < SPL; ++s) M = fmaxf(M, g_m[b*SPL + s]);
            float Zs = 0.f;
            #pragma unroll
            for (int s = 0; s < SPL; ++s) Zs += g_z[b*SPL + s] * __expf(g_m[b*SPL + s] - M);
            sM[b] = M; sInv[b] = 1.0f / Zs;
        }
        __syncthreads();
        int base = (blockIdx.x - BB) * 256 + tid;   // 32 blocks x 256 thr = 8192
        #pragma unroll
        for (int i = 0; i < 4; ++i){
            int idx = base + i * 8192;              // covers 32768 = TT*BB
            int b = idx & (BB-1);
            float s = g_scores[idx];
            float a = __expf(s - sM[b]) * sInv[b];  // masked: s=-inf -> a=0
            out[BB*NN + idx] = a;
            out[BB*NN + TT*BB + idx] = cov[idx] + a;
        }
    }
}

// ---------------------------------------------------------------------------
extern "C" void kernel_launch(void* const* d_in, const int* in_sizes, int n_in,
                              void* d_out, int out_size){
    const float*         dec  = (const float*)d_in[0];          // [B,H]
    const float*         enc  = (const float*)d_in[1];          // [T,B,N]
    const unsigned char* mask = (const unsigned char*)d_in[2];  // [T,B] (dtype auto-detected)
    const float*         cov  = (const float*)d_in[3];          // [T,B]
    const float*         Wd   = (const float*)d_in[4];          // [N,H]
    const float*         bd   = (const float*)d_in[5];          // [N]
    const float*         wc   = (const float*)d_in[6];          // [N]
    const float*         v    = (const float*)d_in[7];          // [N]
    float* out = (float*)d_out;  // c[B,N] | attn[T,B] | coverage_out[T,B]

    k_decfea<<<NN/16, 256>>>(dec, Wd, bd, mask);
    k_main<<<dim3(SPL, BB), THR>>>(enc, cov, wc, v);
    k_combine<<<BB + 32, 256>>>(cov, out);
}

// round 5
// speedup vs baseline: 1.1868x; 1.1868x over previous
#include <cuda_runtime.h>
#include <math.h>

#define TT 2048
#define BB 16
#define NN 2048
#define HH 1024
#define SPL 16
#define CHUNK 128   // 2048/16 timesteps per CTA, 32 macro-iters of 4
#define THR 256     // k_main threads (8 warps), 2 CTAs/SM

// scratch (device globals: no allocation allowed in kernel_launch)
__device__ float g_decfea[BB*NN];
__device__ float g_scores[TT*BB];
__device__ float g_m[BB*SPL];
__device__ float g_z[BB*SPL];
__device__ float g_acc[BB*SPL*NN];
__device__ unsigned char g_mask8[TT*BB];

// single-MUFU tanh (sm_75+), abs err ~2e-4 — fine vs 1e-3 threshold
__device__ __forceinline__ float tanhfast(float x){
    float y;
    asm("tanh.approx.f32 %0, %1;" : "=f"(y) : "f"(x));
    return y;
}

// ---------------------------------------------------------------------------
// Kernel 1: dec_fea[b,n] = dot(dec[b,:], Wd[n,:]) + bd[n].
// Warp-per-row-pair, shuffle-only reduction (no block-wide reduce barriers).
// 128 CTAs x 8 warps x 2 rows = 2048 rows. dec staged in smem 8 batches at a
// time; each smem read feeds both rows of the pair. Also converts the padding
// mask to uint8 (dtype auto-detected): 128x256 = exactly TT*BB lanes.
// ---------------------------------------------------------------------------
__global__ __launch_bounds__(256) void k_decfea(
    const float* __restrict__ dec,
    const float* __restrict__ Wd,
    const float* __restrict__ bd,
    const unsigned char* __restrict__ mraw){
    // ---- mask conversion ----
    {
        const unsigned int* w = (const unsigned int*)mraw;
        int is_word = 1;   // int32 (0/1) or float32 (0.0/1.0) storage
        #pragma unroll
        for (int i = 0; i < 32; ++i){
            unsigned int x = w[i];
            if (x != 0u && x != 1u && x != 0x3F800000u) is_word = 0;
        }
        int idx = blockIdx.x*256 + threadIdx.x;
        unsigned char mv = is_word ? (unsigned char)(w[idx] != 0u)
                                   : (unsigned char)(mraw[idx] != 0);
        g_mask8[idx] = mv;
    }

    __shared__ float sdec[8*HH];       // 32 KB: 8 batches of dec
    int tid  = threadIdx.x;
    int wid  = tid >> 5, lane = tid & 31;
    int n0 = blockIdx.x*16 + wid*2;    // this warp's row pair
    int n1 = n0 + 1;
    const float4* w0p = (const float4*)(Wd + (size_t)n0*HH);
    const float4* w1p = (const float4*)(Wd + (size_t)n1*HH);

    for (int half = 0; half < 2; ++half){
        // stage 8 batches of dec into smem
        const float4* dg = (const float4*)(dec + half*8*HH);
        float4* sg = (float4*)sdec;
        #pragma unroll
        for (int i = 0; i < 8; ++i) sg[tid + i*256] = dg[tid + i*256];
        __syncthreads();

        float acc0[8], acc1[8];
        #pragma unroll
        for (int b = 0; b < 8; ++b){ acc0[b] = 0.f; acc1[b] = 0.f; }
        #pragma unroll
        for (int ch = 0; ch < 8; ++ch){
            float4 wv0 = w0p[ch*32 + lane];   // L1-hot on half==1
            float4 wv1 = w1p[ch*32 + lane];
            #pragma unroll
            for (int b = 0; b < 8; ++b){
                float4 d = ((const float4*)(sdec + b*HH))[ch*32 + lane];
                acc0[b] += wv0.x*d.x + wv0.y*d.y + wv0.z*d.z + wv0.w*d.w;
                acc1[b] += wv1.x*d.x + wv1.y*d.y + wv1.z*d.z + wv1.w*d.w;
            }
        }
        // warp-reduce and store (lane b stores batch b)
        float bias0 = bd[n0], bias1 = bd[n1];
        #pragma unroll
        for (int b = 0; b < 8; ++b){
            float s0 = acc0[b], s1 = acc1[b];
            #pragma unroll
            for (int off = 16; off; off >>= 1){
                s0 += __shfl_xor_sync(0xffffffffu, s0, off);
                s1 += __shfl_xor_sync(0xffffffffu, s1, off);
            }
            int bb = half*8 + b;
            if (lane == 0) g_decfea[bb*NN + n0] = s0 + bias0;
            if (lane == 1) g_decfea[bb*NN + n1] = s1 + bias1;
        }
        __syncthreads();
    }
}

// ---------------------------------------------------------------------------
// Kernel 2: fused scores + online softmax + context partial (flash-style).
// grid (SPL, BB) = 256 CTAs; 256 threads; 2 CTAs/SM (they cover each other's
// reduction/barrier gaps). Each thread owns 8 contiguous n. 4 timesteps per
// macro-iter; 1-iter register prefetch.
// ---------------------------------------------------------------------------
__global__ __launch_bounds__(THR, 2) void k_main(
    const float* __restrict__ enc,
    const float* __restrict__ cov,
    const float* __restrict__ wc,
    const float* __restrict__ v)
{
    __shared__ float scov[CHUNK];
    __shared__ unsigned char smask[CHUNK];
    __shared__ float sred[8][5];      // [warp][score], padded
    __shared__ float sbc[4];
    int tid  = threadIdx.x;
    int wid  = tid >> 5, lane = tid & 31;
    int sp = blockIdx.x, b = blockIdx.y;
    int t0 = sp * CHUNK;

    if (tid < CHUNK){
        scov[tid]  = cov[(t0 + tid)*BB + b];
        smask[tid] = g_mask8[(t0 + tid)*BB + b];
    }
    int n0 = tid * 8;
    float4 df0 = *(const float4*)(g_decfea + b*NN + n0);
    float4 df1 = *(const float4*)(g_decfea + b*NN + n0 + 4);
    float4 w0  = *(const float4*)(wc + n0);
    float4 w1  = *(const float4*)(wc + n0 + 4);
    float4 v0  = *(const float4*)(v + n0);
    float4 v1  = *(const float4*)(v + n0 + 4);

    float m = -INFINITY, Z = 0.f;
    float4 A0 = make_float4(0.f,0.f,0.f,0.f);
    float4 A1 = make_float4(0.f,0.f,0.f,0.f);
    __syncthreads();

    // prefetch batch 0 (4 rows)
    float4 c0[4], c1[4];
    #pragma unroll
    for (int i = 0; i < 4; ++i){
        const float4* rp = (const float4*)(enc + ((size_t)(t0+i)*BB + b)*NN + n0);
        c0[i] = rp[0]; c1[i] = rp[1];
    }
    const int NB = CHUNK/4;   // 32
    for (int it = 0; it < NB; ++it){
        int tb = t0 + it*4;
        bool havenext = (it + 1 < NB);
        float4 x0[4], x1[4];
        if (havenext){
            #pragma unroll
            for (int i = 0; i < 4; ++i){
                const float4* rp = (const float4*)(enc + ((size_t)(tb+4+i)*BB + b)*NN + n0);
                x0[i] = rp[0]; x1[i] = rp[1];
            }
        }
        float part[4];
        #pragma unroll
        for (int i = 0; i < 4; ++i){
            float cv = scov[it*4 + i];
            float p;
            p  = tanhfast(fmaf(cv, w0.x, c0[i].x + df0.x)) * v0.x;
            p += tanhfast(fmaf(cv, w0.y, c0[i].y + df0.y)) * v0.y;
            p += tanhfast(fmaf(cv, w0.z, c0[i].z + df0.z)) * v0.z;
            p += tanhfast(fmaf(cv, w0.w, c0[i].w + df0.w)) * v0.w;
            p += tanhfast(fmaf(cv, w1.x, c1[i].x + df1.x)) * v1.x;
            p += tanhfast(fmaf(cv, w1.y, c1[i].y + df1.y)) * v1.y;
            p += tanhfast(fmaf(cv, w1.z, c1[i].z + df1.z)) * v1.z;
            p += tanhfast(fmaf(cv, w1.w, c1[i].w + df1.w)) * v1.w;
            part[i] = p;
        }
        // stage 1: warp reduce 4 partials
        #pragma unroll
        for (int i = 0; i < 4; ++i)
            #pragma unroll
            for (int off = 16; off; off >>= 1)
                part[i] += __shfl_xor_sync(0xffffffffu, part[i], off);
        if (lane == 0){
            #pragma unroll
            for (int i = 0; i < 4; ++i) sred[wid][i] = part[i];
        }
        __syncthreads();
        // stage 2: 32 threads, 8-lane groups, one score each
        if (tid < 32){
            int s  = tid >> 3;             // score 0..3
            int ww = tid & 7;              // warp 0..7
            float val = sred[ww][s];
            val += __shfl_xor_sync(0xffffffffu, val, 1);
            val += __shfl_xor_sync(0xffffffffu, val, 2);
            val += __shfl_xor_sync(0xffffffffu, val, 4);
            if (ww == 0) sbc[s] = val;
        }
        __syncthreads();
        float s[4];
        #pragma unroll
        for (int i = 0; i < 4; ++i)
            s[i] = smask[it*4 + i] ? -INFINITY : sbc[i];
        if (tid < 4) g_scores[(tb + tid)*BB + b] = s[tid];

        // online softmax update (uniform branch across the block)
        float m2 = m;
        #pragma unroll
        for (int i = 0; i < 4; ++i) m2 = fmaxf(m2, s[i]);
        if (m2 != -INFINITY){
            float sc = __expf(m - m2);             // m==-inf -> 0 (A still 0)
            float p[4];
            #pragma unroll
            for (int i = 0; i < 4; ++i) p[i] = __expf(s[i] - m2);
            Z = Z*sc + (p[0]+p[1]) + (p[2]+p[3]);
            float a;
            a = A0.x*sc; for (int i=0;i<4;++i) a = fmaf(p[i], c0[i].x, a); A0.x = a;
            a = A0.y*sc; for (int i=0;i<4;++i) a = fmaf(p[i], c0[i].y, a); A0.y = a;
            a = A0.z*sc; for (int i=0;i<4;++i) a = fmaf(p[i], c0[i].z, a); A0.z = a;
            a = A0.w*sc; for (int i=0;i<4;++i) a = fmaf(p[i], c0[i].w, a); A0.w = a;
            a = A1.x*sc; for (int i=0;i<4;++i) a = fmaf(p[i], c1[i].x, a); A1.x = a;
            a = A1.y*sc; for (int i=0;i<4;++i) a = fmaf(p[i], c1[i].y, a); A1.y = a;
            a = A1.z*sc; for (int i=0;i<4;++i) a = fmaf(p[i], c1[i].z, a); A1.z = a;
            a = A1.w*sc; for (int i=0;i<4;++i) a = fmaf(p[i], c1[i].w, a); A1.w = a;
            m = m2;
        }
        if (havenext){
            #pragma unroll
            for (int i = 0; i < 4; ++i){ c0[i] = x0[i]; c1[i] = x1[i]; }
        }
    }
    if (tid == 0){
        g_m[b*SPL + sp] = m;
        g_z[b*SPL + sp] = Z;
    }
    float4* op = (float4*)(g_acc + (size_t)(b*SPL + sp)*NN + n0);
    op[0] = A0; op[1] = A1;
}

// ---------------------------------------------------------------------------
// Kernel 3: combine. blocks 0..15: context c[b,:] (16 split partials).
// blocks 16..143: attn + coverage, float4 over the flat (t*16+b) index.
// ---------------------------------------------------------------------------
__global__ void k_combine(const float* __restrict__ cov,
                          float* __restrict__ out){
    int tid = threadIdx.x;
    if (blockIdx.x < BB){
        // ---- context for batch b ----
        int b = blockIdx.x;
        __shared__ float sw[SPL];
        if (tid < 32){
            float mv = (tid < SPL) ? g_m[b*SPL + tid] : -INFINITY;
            float zv = (tid < SPL) ? g_z[b*SPL + tid] : 0.f;
            float M = mv;
            #pragma unroll
            for (int off = 16; off; off >>= 1)
                M = fmaxf(M, __shfl_xor_sync(0xffffffffu, M, off));
            float zz = zv * __expf(mv - M);
            float Zs = zz;
            #pragma unroll
            for (int off = 16; off; off >>= 1)
                Zs += __shfl_xor_sync(0xffffffffu, Zs, off);
            float inv = 1.0f / Zs;
            if (tid < SPL) sw[tid] = __expf(mv - M) * inv;
        }
        __syncthreads();
        int n0 = tid * 8;
        float4 r0 = make_float4(0.f,0.f,0.f,0.f);
        float4 r1 = make_float4(0.f,0.f,0.f,0.f);
        #pragma unroll
        for (int s = 0; s < SPL; ++s){
            const float4* p = (const float4*)(g_acc + (size_t)(b*SPL + s)*NN + n0);
            float wgt = sw[s];
            float4 x = p[0], y = p[1];
            r0.x = fmaf(wgt, x.x, r0.x); r0.y = fmaf(wgt, x.y, r0.y);
            r0.z = fmaf(wgt, x.z, r0.z); r0.w = fmaf(wgt, x.w, r0.w);
            r1.x = fmaf(wgt, y.x, r1.x); r1.y = fmaf(wgt, y.y, r1.y);
            r1.z = fmaf(wgt, y.z, r1.z); r1.w = fmaf(wgt, y.w, r1.w);
        }
        float4* co = (float4*)(out + b*NN + n0);
        co[0] = r0; co[1] = r1;
    } else {
        // ---- attn_dist + coverage_out, float4-flat-indexed ----
        __shared__ float sM[BB], sInv[BB];
        if (tid < BB){
            int b = tid;
            float M = -INFINITY;
            #pragma unroll
            for (int s = 0; s < SPL; ++s) M = fmaxf(M, g_m[b*SPL + s]);
            float Zs = 0.f;
            #pragma unroll
            for (int s = 0; s < SPL; ++s) Zs += g_z[b*SPL + s] * __expf(g_m[b*SPL + s] - M);
            sM[b] = M; sInv[b] = 1.0f / Zs;
        }
        __syncthreads();
        int q = (blockIdx.x - BB) * 256 + tid;      // 128 blocks x 256 thr = 32768 quads... /4
        int flat = q * 4;                           // covers TT*BB = 32768 floats -> q < 8192
        if (q < (TT*BB)/4){
            float4 sc = *(const float4*)(g_scores + flat);
            float4 cv = *(const float4*)(cov + flat);
            int b0 = flat & (BB-1);                 // flat..flat+3 consecutive
            float4 a;
            a.x = __expf(sc.x - sM[b0  ]) * sInv[b0  ];
            a.y = __expf(sc.y - sM[b0+1]) * sInv[b0+1];
            a.z = __expf(sc.z - sM[b0+2]) * sInv[b0+2];
            a.w = __expf(sc.w - sM[b0+3]) * sInv[b0+3];
            *(float4*)(out + BB*NN + flat) = a;
            float4 cg = make_float4(cv.x + a.x, cv.y + a.y, cv.z + a.z, cv.w + a.w);
            *(float4*)(out + BB*NN + TT*BB + flat) = cg;
        }
    }
}

// ---------------------------------------------------------------------------
extern "C" void kernel_launch(void* const* d_in, const int* in_sizes, int n_in,
                              void* d_out, int out_size){
    const float*         dec  = (const float*)d_in[0];          // [B,H]
    const float*         enc  = (const float*)d_in[1];          // [T,B,N]
    const unsigned char* mask = (const unsigned char*)d_in[2];  // [T,B] (dtype auto-detected)
    const float*         cov  = (const float*)d_in[3];          // [T,B]
    const float*         Wd   = (const float*)d_in[4];          // [N,H]
    const float*         bd   = (const float*)d_in[5];          // [N]
    const float*         wc   = (const float*)d_in[6];          // [N]
    const float*         v    = (const float*)d_in[7];          // [N]
    float* out = (float*)d_out;  // c[B,N] | attn[T,B] | coverage_out[T,B]

    k_decfea<<<128, 256>>>(dec, Wd, bd, mask);
    k_main<<<dim3(SPL, BB), THR>>>(enc, cov, wc, v);
    k_combine<<<BB + (TT*BB/4 + 255)/256, 256>>>(cov, out);
}

// round 6
// speedup vs baseline: 1.2451x; 1.0491x over previous
#include <cuda_runtime.h>
#include <math.h>

#define TT 2048
#define BB 16
#define NN 2048
#define HH 1024
#define SPL 32
#define CHUNK 64    // 2048/32 timesteps per CTA, 16 macro-iters of 4
#define THR 256     // k_main threads (8 warps), 2 CTAs/SM

// scratch (device globals: no allocation allowed in kernel_launch)
__device__ float g_decfea[BB*NN];
__device__ float g_scores[TT*BB];
__device__ float g_m[BB*SPL];
__device__ float g_z[BB*SPL];
__device__ float g_acc[BB*SPL*NN];     // 4 MB
__device__ unsigned char g_mask8[TT*BB];

// single-MUFU tanh (sm_75+), abs err ~2e-4 — fine vs 1e-3 threshold
__device__ __forceinline__ float tanhfast(float x){
    float y;
    asm("tanh.approx.f32 %0, %1;" : "=f"(y) : "f"(x));
    return y;
}

__device__ __forceinline__ float4 ldcs4(const float4* p){
    float4 r;
    asm("ld.global.cs.v4.f32 {%0,%1,%2,%3}, [%4];"
        : "=f"(r.x), "=f"(r.y), "=f"(r.z), "=f"(r.w) : "l"(p));
    return r;
}

// ---------------------------------------------------------------------------
// Kernel 1: dec_fea[b,n] = dot(dec[b,:], Wd[n,:]) + bd[n].
// 256 CTAs x 128 thr (4 warps); warp owns a row pair; all 16 dec batches
// staged in smem once (64 KB). Shuffle-only reduction. Also converts the
// padding mask to uint8 (dtype auto-detected): 256x128 = exactly TT*BB lanes.
// ---------------------------------------------------------------------------
__global__ __launch_bounds__(128) void k_decfea(
    const float* __restrict__ dec,
    const float* __restrict__ Wd,
    const float* __restrict__ bd,
    const unsigned char* __restrict__ mraw){
    // ---- mask conversion ----
    {
        const unsigned int* w = (const unsigned int*)mraw;
        int is_word = 1;   // int32 (0/1) or float32 (0.0/1.0) storage
        #pragma unroll
        for (int i = 0; i < 32; ++i){
            unsigned int x = w[i];
            if (x != 0u && x != 1u && x != 0x3F800000u) is_word = 0;
        }
        int idx = blockIdx.x*128 + threadIdx.x;
        unsigned char mv = is_word ? (unsigned char)(w[idx] != 0u)
                                   : (unsigned char)(mraw[idx] != 0);
        g_mask8[idx] = mv;
    }

    __shared__ float sdec[BB*HH];      // 64 KB: all 16 batches of dec
    int tid  = threadIdx.x;
    int wid  = tid >> 5, lane = tid & 31;

    // stage all of dec
    {
        const float4* dg = (const float4*)dec;
        float4* sg = (float4*)sdec;
        #pragma unroll
        for (int i = 0; i < 32; ++i) sg[tid + i*128] = dg[tid + i*128];
    }
    __syncthreads();

    int n0 = blockIdx.x*8 + wid*2;     // this warp's row pair
    int n1 = n0 + 1;
    const float4* w0p = (const float4*)(Wd + (size_t)n0*HH);
    const float4* w1p = (const float4*)(Wd + (size_t)n1*HH);

    float acc0[BB], acc1[BB];
    #pragma unroll
    for (int b = 0; b < BB; ++b){ acc0[b] = 0.f; acc1[b] = 0.f; }

    #pragma unroll
    for (int ch = 0; ch < 8; ++ch){
        float4 wv0 = w0p[ch*32 + lane];
        float4 wv1 = w1p[ch*32 + lane];
        #pragma unroll
        for (int b = 0; b < BB; ++b){
            float4 d = ((const float4*)sdec)[b*256 + ch*32 + lane];
            acc0[b] += wv0.x*d.x + wv0.y*d.y + wv0.z*d.z + wv0.w*d.w;
            acc1[b] += wv1.x*d.x + wv1.y*d.y + wv1.z*d.z + wv1.w*d.w;
        }
    }
    float bias0 = bd[n0], bias1 = bd[n1];
    #pragma unroll
    for (int b = 0; b < BB; ++b){
        float s0 = acc0[b], s1 = acc1[b];
        #pragma unroll
        for (int off = 16; off; off >>= 1){
            s0 += __shfl_xor_sync(0xffffffffu, s0, off);
            s1 += __shfl_xor_sync(0xffffffffu, s1, off);
        }
        if (lane == 0) g_decfea[b*NN + n0] = s0 + bias0;
        if (lane == 1) g_decfea[b*NN + n1] = s1 + bias1;
    }
}

// ---------------------------------------------------------------------------
// Kernel 2: fused scores + online softmax + context partial (flash-style).
// grid (SPL, BB) = 512 CTAs; 256 threads; 2 CTAs/SM -> ~1.7 waves of 296
// slots so the scheduler self-balances. Each thread owns 8 contiguous n;
// 4 timesteps per macro-iter; 1-iter register prefetch; streaming loads.
// ---------------------------------------------------------------------------
__global__ __launch_bounds__(THR, 2) void k_main(
    const float* __restrict__ enc,
    const float* __restrict__ cov,
    const float* __restrict__ wc,
    const float* __restrict__ v)
{
    __shared__ float scov[CHUNK];
    __shared__ unsigned char smask[CHUNK];
    __shared__ float sred[8][5];      // [warp][score], padded
    __shared__ float sbc[4];
    int tid  = threadIdx.x;
    int wid  = tid >> 5, lane = tid & 31;
    int sp = blockIdx.x, b = blockIdx.y;
    int t0 = sp * CHUNK;

    if (tid < CHUNK){
        scov[tid]  = cov[(t0 + tid)*BB + b];
        smask[tid] = g_mask8[(t0 + tid)*BB + b];
    }
    int n0 = tid * 8;
    float4 df0 = *(const float4*)(g_decfea + b*NN + n0);
    float4 df1 = *(const float4*)(g_decfea + b*NN + n0 + 4);
    float4 w0  = *(const float4*)(wc + n0);
    float4 w1  = *(const float4*)(wc + n0 + 4);
    float4 v0  = *(const float4*)(v + n0);
    float4 v1  = *(const float4*)(v + n0 + 4);

    float m = -INFINITY, Z = 0.f;
    float4 A0 = make_float4(0.f,0.f,0.f,0.f);
    float4 A1 = make_float4(0.f,0.f,0.f,0.f);
    __syncthreads();

    // prefetch batch 0 (4 rows)
    float4 c0[4], c1[4];
    #pragma unroll
    for (int i = 0; i < 4; ++i){
        const float4* rp = (const float4*)(enc + ((size_t)(t0+i)*BB + b)*NN + n0);
        c0[i] = ldcs4(rp); c1[i] = ldcs4(rp + 1);
    }
    const int NB = CHUNK/4;   // 16
    for (int it = 0; it < NB; ++it){
        int tb = t0 + it*4;
        bool havenext = (it + 1 < NB);
        float4 x0[4], x1[4];
        if (havenext){
            #pragma unroll
            for (int i = 0; i < 4; ++i){
                const float4* rp = (const float4*)(enc + ((size_t)(tb+4+i)*BB + b)*NN + n0);
                x0[i] = ldcs4(rp); x1[i] = ldcs4(rp + 1);
            }
        }
        float part[4];
        #pragma unroll
        for (int i = 0; i < 4; ++i){
            float cv = scov[it*4 + i];
            float p;
            p  = tanhfast(fmaf(cv, w0.x, c0[i].x + df0.x)) * v0.x;
            p += tanhfast(fmaf(cv, w0.y, c0[i].y + df0.y)) * v0.y;
            p += tanhfast(fmaf(cv, w0.z, c0[i].z + df0.z)) * v0.z;
            p += tanhfast(fmaf(cv, w0.w, c0[i].w + df0.w)) * v0.w;
            p += tanhfast(fmaf(cv, w1.x, c1[i].x + df1.x)) * v1.x;
            p += tanhfast(fmaf(cv, w1.y, c1[i].y + df1.y)) * v1.y;
            p += tanhfast(fmaf(cv, w1.z, c1[i].z + df1.z)) * v1.z;
            p += tanhfast(fmaf(cv, w1.w, c1[i].w + df1.w)) * v1.w;
            part[i] = p;
        }
        // stage 1: warp reduce 4 partials
        #pragma unroll
        for (int i = 0; i < 4; ++i)
            #pragma unroll
            for (int off = 16; off; off >>= 1)
                part[i] += __shfl_xor_sync(0xffffffffu, part[i], off);
        if (lane == 0){
            #pragma unroll
            for (int i = 0; i < 4; ++i) sred[wid][i] = part[i];
        }
        __syncthreads();
        // stage 2: 32 threads, 8-lane groups, one score each
        if (tid < 32){
            int s  = tid >> 3;             // score 0..3
            int ww = tid & 7;              // warp 0..7
            float val = sred[ww][s];
            val += __shfl_xor_sync(0xffffffffu, val, 1);
            val += __shfl_xor_sync(0xffffffffu, val, 2);
            val += __shfl_xor_sync(0xffffffffu, val, 4);
            if (ww == 0) sbc[s] = val;
        }
        __syncthreads();
        float s[4];
        #pragma unroll
        for (int i = 0; i < 4; ++i)
            s[i] = smask[it*4 + i] ? -INFINITY : sbc[i];
        if (tid < 4) g_scores[(tb + tid)*BB + b] = s[tid];

        // online softmax update (uniform branch across the block)
        float m2 = m;
        #pragma unroll
        for (int i = 0; i < 4; ++i) m2 = fmaxf(m2, s[i]);
        if (m2 != -INFINITY){
            float sc = __expf(m - m2);             // m==-inf -> 0 (A still 0)
            float p[4];
            #pragma unroll
            for (int i = 0; i < 4; ++i) p[i] = __expf(s[i] - m2);
            Z = Z*sc + (p[0]+p[1]) + (p[2]+p[3]);
            float a;
            a = A0.x*sc; for (int i=0;i<4;++i) a = fmaf(p[i], c0[i].x, a); A0.x = a;
            a = A0.y*sc; for (int i=0;i<4;++i) a = fmaf(p[i], c0[i].y, a); A0.y = a;
            a = A0.z*sc; for (int i=0;i<4;++i) a = fmaf(p[i], c0[i].z, a); A0.z = a;
            a = A0.w*sc; for (int i=0;i<4;++i) a = fmaf(p[i], c0[i].w, a); A0.w = a;
            a = A1.x*sc; for (int i=0;i<4;++i) a = fmaf(p[i], c1[i].x, a); A1.x = a;
            a = A1.y*sc; for (int i=0;i<4;++i) a = fmaf(p[i], c1[i].y, a); A1.y = a;
            a = A1.z*sc; for (int i=0;i<4;++i) a = fmaf(p[i], c1[i].z, a); A1.z = a;
            a = A1.w*sc; for (int i=0;i<4;++i) a = fmaf(p[i], c1[i].w, a); A1.w = a;
            m = m2;
        }
        if (havenext){
            #pragma unroll
            for (int i = 0; i < 4; ++i){ c0[i] = x0[i]; c1[i] = x1[i]; }
        }
    }
    if (tid == 0){
        g_m[b*SPL + sp] = m;
        g_z[b*SPL + sp] = Z;
    }
    float4* op = (float4*)(g_acc + (size_t)(b*SPL + sp)*NN + n0);
    op[0] = A0; op[1] = A1;
}

// ---------------------------------------------------------------------------
// Kernel 3: combine. blocks 0..15: context c[b,:] (32 split partials; the
// split-stat reduce is exactly one warp). blocks 16..: attn + coverage,
// float4 over the flat (t*16+b) index.
// ---------------------------------------------------------------------------
__global__ void k_combine(const float* __restrict__ cov,
                          float* __restrict__ out){
    int tid = threadIdx.x;
    if (blockIdx.x < BB){
        // ---- context for batch b ----
        int b = blockIdx.x;
        __shared__ float sw[SPL];
        if (tid < 32){
            float mv = g_m[b*SPL + tid];
            float zv = g_z[b*SPL + tid];
            float M = mv;
            #pragma unroll
            for (int off = 16; off; off >>= 1)
                M = fmaxf(M, __shfl_xor_sync(0xffffffffu, M, off));
            float zz = zv * __expf(mv - M);
            float Zs = zz;
            #pragma unroll
            for (int off = 16; off; off >>= 1)
                Zs += __shfl_xor_sync(0xffffffffu, Zs, off);
            float inv = 1.0f / Zs;
            sw[tid] = __expf(mv - M) * inv;
        }
        __syncthreads();
        int n0 = tid * 8;
        float4 r0 = make_float4(0.f,0.f,0.f,0.f);
        float4 r1 = make_float4(0.f,0.f,0.f,0.f);
        #pragma unroll
        for (int s = 0; s < SPL; ++s){
            const float4* p = (const float4*)(g_acc + (size_t)(b*SPL + s)*NN + n0);
            float wgt = sw[s];
            float4 x = p[0], y = p[1];
            r0.x = fmaf(wgt, x.x, r0.x); r0.y = fmaf(wgt, x.y, r0.y);
            r0.z = fmaf(wgt, x.z, r0.z); r0.w = fmaf(wgt, x.w, r0.w);
            r1.x = fmaf(wgt, y.x, r1.x); r1.y = fmaf(wgt, y.y, r1.y);
            r1.z = fmaf(wgt, y.z, r1.z); r1.w = fmaf(wgt, y.w, r1.w);
        }
        float4* co = (float4*)(out + b*NN + n0);
        co[0] = r0; co[1] = r1;
    } else {
        // ---- attn_dist + coverage_out, float4-flat-indexed ----
        __shared__ float sM[BB], sInv[BB];
        if (tid < BB){
            int b = tid;
            float M = -INFINITY;
            #pragma unroll
            for (int s = 0; s < SPL; ++s) M = fmaxf(M, g_m[b*SPL + s]);
            float Zs = 0.f;
            #pragma unroll
            for (int s = 0; s < SPL; ++s) Zs += g_z[b*SPL + s] * __expf(g_m[b*SPL + s] - M);
            sM[b] = M; sInv[b] = 1.0f / Zs;
        }
        __syncthreads();
        int q = (blockIdx.x - BB) * 256 + tid;
        int flat = q * 4;                           // covers TT*BB = 32768 floats
        if (q < (TT*BB)/4){
            float4 sc = *(const float4*)(g_scores + flat);
            float4 cv = *(const float4*)(cov + flat);
            int b0 = flat & (BB-1);                 // 4 consecutive batches
            float4 a;
            a.x = __expf(sc.x - sM[b0  ]) * sInv[b0  ];
            a.y = __expf(sc.y - sM[b0+1]) * sInv[b0+1];
            a.z = __expf(sc.z - sM[b0+2]) * sInv[b0+2];
            a.w = __expf(sc.w - sM[b0+3]) * sInv[b0+3];
            *(float4*)(out + BB*NN + flat) = a;
            float4 cg = make_float4(cv.x + a.x, cv.y + a.y, cv.z + a.z, cv.w + a.w);
            *(float4*)(out + BB*NN + TT*BB + flat) = cg;
        }
    }
}

// ---------------------------------------------------------------------------
extern "C" void kernel_launch(void* const* d_in, const int* in_sizes, int n_in,
                              void* d_out, int out_size){
    const float*         dec  = (const float*)d_in[0];          // [B,H]
    const float*         enc  = (const float*)d_in[1];          // [T,B,N]
    const unsigned char* mask = (const unsigned char*)d_in[2];  // [T,B] (dtype auto-detected)
    const float*         cov  = (const float*)d_in[3];          // [T,B]
    const float*         Wd   = (const float*)d_in[4];          // [N,H]
    const float*         bd   = (const float*)d_in[5];          // [N]
    const float*         wc   = (const float*)d_in[6];          // [N]
    const float*         v    = (const float*)d_in[7];          // [N]
    float* out = (float*)d_out;  // c[B,N] | attn[T,B] | coverage_out[T,B]

    k_decfea<<<256, 128>>>(dec, Wd, bd, mask);
    k_main<<<dim3(SPL, BB), THR>>>(enc, cov, wc, v);
    k_combine<<<BB + (TT*BB/4 + 255)/256, 256>>>(cov, out);
}